// round 5
// baseline (speedup 1.0000x reference)
#include <cuda_runtime.h>
#include <cuda_bf16.h>
#include <cstdint>
#include <math.h>

// Problem constants
#define Bn   32
#define Sn   2048
#define En   512
#define Vn   32000
#define NGRP 16      // batch groups
#define CPG  8       // CTAs per group (column split of W_dec)
#define NCOL 64      // columns per CTA
#define NTHR 256
#define SQRT_E 22.627416997969522f
#define EPSLN 1e-6f

// padded z layout: 4 blocks of 128 floats, each padded to 132 (bank-conflict-free h-split)
#define ZBLK 132
#define ZROW (4 * ZBLK)          // 528 floats per batch
#define ZIDX(b, i) ((b) * ZROW + ((i) >> 7) * ZBLK + ((i) & 127))

// ---------- static device scratch ----------
__device__ float    g_u[2 * NGRP * 2 * En];          // double-buffered u exchange
__device__ unsigned g_ctr[NGRP * 32];                 // monotonic counters, 128B apart
__device__ float    g_logits[(size_t)Bn * Vn];       // 4.1 MB logits scratch

// ---------- sync / PTX helpers ----------
__device__ __forceinline__ unsigned ld_acquire_u32(const unsigned* p) {
    unsigned v;
    asm volatile("ld.acquire.gpu.global.u32 %0, [%1];" : "=r"(v) : "l"(p) : "memory");
    return v;
}
__device__ __forceinline__ void red_release_add(unsigned* p, unsigned v) {
    asm volatile("red.release.gpu.global.add.u32 [%0], %1;" :: "l"(p), "r"(v) : "memory");
}
// packed f32x2 FMA (Blackwell FFMA2): d += a * b (two independent IEEE fp32 lanes)
__device__ __forceinline__ void fma2(unsigned long long& d, unsigned long long a, unsigned long long b) {
    asm("fma.rn.f32x2 %0, %1, %2, %0;" : "+l"(d) : "l"(a), "l"(b));
}
__device__ __forceinline__ unsigned long long add2(unsigned long long a, unsigned long long b) {
    unsigned long long r; asm("add.rn.f32x2 %0, %1, %2;" : "=l"(r) : "l"(a), "l"(b)); return r;
}
__device__ __forceinline__ float lo2(unsigned long long v) {
    float a, b; asm("mov.b64 {%0, %1}, %2;" : "=f"(a), "=f"(b) : "l"(v)); return a;
}
__device__ __forceinline__ float hi2(unsigned long long v) {
    float a, b; asm("mov.b64 {%0, %1}, %2;" : "=f"(a), "=f"(b) : "l"(v)); return b;
}

// ===================== Kernel 1: recurrent scan =====================
// grid = 128 CTAs (16 groups x 8), 256 threads. CTA (g,c) keeps
// W_dec[:, 64c:64c+64) in registers: thread (j = tid>>2, h = tid&3) holds
// rows [h*128, h*128+128) of column J = 64c+j, packed as 64 x f32x2.
// Per step: register matvec (both batches) -> 2 warp shuffles -> h0 lanes
// hold full u -> per-warp STG + release -> all-warp poll -> warp-redundant
// stats from the loaded u row -> layernorm fused with next emb add.
// ONE syncthreads + ONE syncwarp per step.
__global__ void __launch_bounds__(NTHR, 1)
rnn_scan_kernel(const int* __restrict__ seq,
                const float* __restrict__ emb,
                const float* __restrict__ Wdec,
                const float* __restrict__ bdec,
                const float* __restrict__ gamma,
                const float* __restrict__ beta,
                float* __restrict__ outz)
{
    __shared__ __align__(16) float zs[2 * ZROW];   // padded 2-batch state
    __shared__ __align__(16) float gs[En], bs_[En], bd[En];

    const int tid = threadIdx.x;
    const int g   = blockIdx.x >> 3;
    const int c   = blockIdx.x & 7;

    // matvec roles
    const int j = tid >> 2;                  // local column 0..63
    const int h = tid & 3;                   // 4-way row split (128 rows each)
    const int J = c * NCOL + j;              // global column
    // LN / emb roles
    const int be = tid >> 7;                 // batch half
    const int j4 = (tid << 2) & (En - 1);    // own float4 base
    const int lane = tid & 31;
    const int kown = (tid >> 5) & 3;         // which of the 4 row-loads holds j4
    const int brow = 2 * g + be;

    // ---- init: W column slice into registers (row pairs packed for f32x2) ----
    unsigned long long Wp[64];
    {
        const float* Wb = Wdec + (size_t)(h * 128) * En + J;
        #pragma unroll
        for (int k = 0; k < 64; ++k) {
            float w0 = __ldg(Wb + (size_t)(2 * k) * En);
            float w1 = __ldg(Wb + (size_t)(2 * k + 1) * En);
            asm("mov.b64 %0, {%1, %2};" : "=l"(Wp[k]) : "f"(w0), "f"(w1));
        }
    }
    for (int n = tid; n < En; n += NTHR) { gs[n] = gamma[n]; bs_[n] = beta[n]; bd[n] = bdec[n]; }
    // zs init: z_0 = sqrt(E) * x_0
    {
        int idx = __ldg(&seq[brow * Sn + 0]);
        float4 e0 = __ldg((const float4*)&emb[(size_t)idx * En + j4]);
        float4 z0 = make_float4(e0.x * SQRT_E, e0.y * SQRT_E, e0.z * SQRT_E, e0.w * SQRT_E);
        *(float4*)&zs[ZIDX(be, j4)] = z0;
    }

    unsigned* ctr = &g_ctr[g * 32];

    for (int t = 0; t < Sn; ++t) {
        __syncthreads();   // B1: zs consistent for matvec

        // prefetch next embedding (used at step end)
        float4 epre = make_float4(0.f, 0.f, 0.f, 0.f);
        if (t + 1 < Sn) {
            int idx = __ldg(&seq[brow * Sn + (t + 1)]);
            epre = __ldg((const float4*)&emb[(size_t)idx * En + j4]);
        }

        const int buf = t & 1;
        float* gu = &g_u[((buf * NGRP + g) * 2) * En];   // [2][512] for this (buf,group)

        // ---- matvec: 128 rows x 1 col x 2 batches, packed f32x2 ----
        {
            unsigned long long a0e = 0ull, a0o = 0ull, a1e = 0ull, a1o = 0ull;
            const ulonglong2* zp0 = (const ulonglong2*)&zs[h * ZBLK];
            const ulonglong2* zp1 = (const ulonglong2*)&zs[ZROW + h * ZBLK];
            #pragma unroll
            for (int kk = 0; kk < 32; ++kk) {
                ulonglong2 za = zp0[kk];
                ulonglong2 zb = zp1[kk];
                fma2(a0e, Wp[2 * kk + 0], za.x);
                fma2(a0o, Wp[2 * kk + 1], za.y);
                fma2(a1e, Wp[2 * kk + 0], zb.x);
                fma2(a1o, Wp[2 * kk + 1], zb.y);
            }
            unsigned long long s0 = add2(a0e, a0o);
            unsigned long long s1 = add2(a1e, a1o);
            float mv0 = lo2(s0) + hi2(s0);
            float mv1 = lo2(s1) + hi2(s1);
            // combine the 4 h-partials (lanes differ in bits 0-1)
            mv0 += __shfl_xor_sync(~0u, mv0, 1);
            mv1 += __shfl_xor_sync(~0u, mv1, 1);
            mv0 += __shfl_xor_sync(~0u, mv0, 2);
            mv1 += __shfl_xor_sync(~0u, mv1, 2);
            if (h == 0) {
                float u0 = zs[ZIDX(0, J)] + mv0 + bd[J];
                float u1 = zs[ZIDX(1, J)] + mv1 + bd[J];
                gu[J]      = u0;
                gu[En + J] = u1;
            }
        }
        __syncwarp();
        if (lane == 0) red_release_add(ctr, 1u);   // per-warp arrival (64 per group-step)

        // ---- poll until all 64 warps of the group arrived ----
        {
            const unsigned tgt = 64u * (unsigned)(t + 1);
            while (ld_acquire_u32(ctr) < tgt) { }
        }

        // ---- warp-redundant stats over the full u row + LN + fused emb add ----
        {
            const float* ub = &gu[be * En];
            float4 q0 = __ldcg((const float4*)&ub[0 * 128 + lane * 4]);
            float4 q1 = __ldcg((const float4*)&ub[1 * 128 + lane * 4]);
            float4 q2 = __ldcg((const float4*)&ub[2 * 128 + lane * 4]);
            float4 q3 = __ldcg((const float4*)&ub[3 * 128 + lane * 4]);
            float s1 = (q0.x + q0.y + q0.z + q0.w) + (q1.x + q1.y + q1.z + q1.w)
                     + (q2.x + q2.y + q2.z + q2.w) + (q3.x + q3.y + q3.z + q3.w);
            float s2 = q0.x*q0.x + q0.y*q0.y + q0.z*q0.z + q0.w*q0.w
                     + q1.x*q1.x + q1.y*q1.y + q1.z*q1.z + q1.w*q1.w
                     + q2.x*q2.x + q2.y*q2.y + q2.z*q2.z + q2.w*q2.w
                     + q3.x*q3.x + q3.y*q3.y + q3.z*q3.z + q3.w*q3.w;
            #pragma unroll
            for (int off = 16; off; off >>= 1) {
                s1 += __shfl_xor_sync(~0u, s1, off);
                s2 += __shfl_xor_sync(~0u, s2, off);
            }
            float mu = s1 * (1.f / En);
            float va = (s2 - (float)En * mu * mu) * (1.f / (En - 1));
            float rv = __fdividef(1.f, sqrtf(va) + EPSLN);

            float4 uu = (kown == 0) ? q0 : (kown == 1) ? q1 : (kown == 2) ? q2 : q3;
            float4 gg = *(float4*)&gs[j4];
            float4 bb = *(float4*)&bs_[j4];
            float4 zn;
            zn.x = fmaf(gg.x, (uu.x - mu) * rv, bb.x) + SQRT_E * epre.x;
            zn.y = fmaf(gg.y, (uu.y - mu) * rv, bb.y) + SQRT_E * epre.y;
            zn.z = fmaf(gg.z, (uu.z - mu) * rv, bb.z) + SQRT_E * epre.z;
            zn.w = fmaf(gg.w, (uu.w - mu) * rv, bb.w) + SQRT_E * epre.w;
            *(float4*)&zs[ZIDX(be, j4)] = zn;
        }
        // loop-top syncthreads orders these writes before the next matvec.
    }

    // final z (last step added no embedding) -> d_out, CTA c==0 writes
    if (c == 0) {
        float4 zf = *(float4*)&zs[ZIDX(be, j4)];
        *(float4*)&outz[brow * En + j4] = zf;
    }
}

// ===================== Kernel 2: logits = z @ W_voc + b_voc =====================
__global__ void __launch_bounds__(128)
vocab_gemm_kernel(const float* __restrict__ z,
                  const float* __restrict__ Wvoc,
                  const float* __restrict__ bvoc)
{
    extern __shared__ float zsh[];   // 32*512 floats = 64 KB
    for (int n = threadIdx.x; n < (Bn * En) / 4; n += 128)
        ((float4*)zsh)[n] = ((const float4*)z)[n];
    __syncthreads();

    const int v = blockIdx.x * 128 + threadIdx.x;
    float bias = __ldg(&bvoc[v]);
    float acc[Bn];
    #pragma unroll
    for (int b = 0; b < Bn; ++b) acc[b] = bias;

    for (int i = 0; i < En; i += 4) {
        float w0 = __ldg(&Wvoc[(size_t)(i + 0) * Vn + v]);
        float w1 = __ldg(&Wvoc[(size_t)(i + 1) * Vn + v]);
        float w2 = __ldg(&Wvoc[(size_t)(i + 2) * Vn + v]);
        float w3 = __ldg(&Wvoc[(size_t)(i + 3) * Vn + v]);
        #pragma unroll
        for (int b = 0; b < Bn; ++b) {
            float4 zz = *(const float4*)&zsh[b * En + i];
            acc[b] = fmaf(zz.x, w0, fmaf(zz.y, w1, fmaf(zz.z, w2, fmaf(zz.w, w3, acc[b]))));
        }
    }
    #pragma unroll
    for (int b = 0; b < Bn; ++b)
        g_logits[(size_t)b * Vn + v] = acc[b];
}

// ===================== Kernel 3: log_softmax + counter reset =====================
__global__ void __launch_bounds__(256)
logsoftmax_kernel(float* __restrict__ dout)
{
    __shared__ float sb[34];
    const int row = blockIdx.x;
    const int tid = threadIdx.x;
    if (row == 0 && tid < NGRP) g_ctr[tid * 32] = 0u;   // reset for next graph replay

    const float* L = &g_logits[(size_t)row * Vn];

    float m = -INFINITY;
    for (int v = tid; v < Vn; v += 256) m = fmaxf(m, __ldg(&L[v]));
    #pragma unroll
    for (int off = 16; off; off >>= 1) m = fmaxf(m, __shfl_xor_sync(~0u, m, off));
    if ((tid & 31) == 0) sb[tid >> 5] = m;
    __syncthreads();
    if (tid < 8) {
        float mm = sb[tid];
        #pragma unroll
        for (int off = 4; off; off >>= 1) mm = fmaxf(mm, __shfl_xor_sync(0xffu, mm, off));
        if (tid == 0) sb[32] = mm;
    }
    __syncthreads();
    const float M = sb[32];
    __syncthreads();

    float s = 0.f;
    for (int v = tid; v < Vn; v += 256) s += expf(__ldg(&L[v]) - M);
    #pragma unroll
    for (int off = 16; off; off >>= 1) s += __shfl_xor_sync(~0u, s, off);
    if ((tid & 31) == 0) sb[tid >> 5] = s;
    __syncthreads();
    if (tid < 8) {
        float ss = sb[tid];
        #pragma unroll
        for (int off = 4; off; off >>= 1) ss += __shfl_xor_sync(0xffu, ss, off);
        if (tid == 0) sb[33] = ss;
    }
    __syncthreads();
    const float lse = M + logf(sb[33]);

    float* Y = dout + Bn * En + (size_t)row * Vn;
    for (int v = tid; v < Vn; v += 256) Y[v] = __ldg(&L[v]) - lse;
}

// ===================== launch =====================
extern "C" void kernel_launch(void* const* d_in, const int* in_sizes, int n_in,
                              void* d_out, int out_size)
{
    // inputs: hidden_state, output_sequence, emb_out, W_dec, b_dec, gamma, beta, W_voc, b_voc
    const int*   seq   = (const int*)  d_in[1];
    const float* emb   = (const float*)d_in[2];
    const float* Wdec  = (const float*)d_in[3];
    const float* bdec  = (const float*)d_in[4];
    const float* gamma = (const float*)d_in[5];
    const float* beta  = (const float*)d_in[6];
    const float* Wvoc  = (const float*)d_in[7];
    const float* bvoc  = (const float*)d_in[8];
    float* out = (float*)d_out;

    const int smem2 = Bn * En * (int)sizeof(float);   // 64 KB
    cudaFuncSetAttribute(vocab_gemm_kernel, cudaFuncAttributeMaxDynamicSharedMemorySize, smem2);

    rnn_scan_kernel<<<NGRP * CPG, NTHR>>>(seq, emb, Wdec, bdec, gamma, beta, out);
    vocab_gemm_kernel<<<Vn / 128, 128, smem2>>>(out, Wvoc, bvoc);
    logsoftmax_kernel<<<Bn, 256>>>(out);
}